// round 15
// baseline (speedup 1.0000x reference)
#include <cuda_runtime.h>
#include <math.h>

#define SLEN 256
#define BSZ  64
#define DIM  1024
#define HID  512
#define NT   17
#define G4   (4*HID)    // 2048 gate rows per direction
#define NCOLS (2*G4)    // 4096 combined columns (fwd+bwd)
#define NROWS (SLEN*BSZ)

// ---------------- device scratch (no allocations allowed) ----------------
__device__ float d_xg[(size_t)2*SLEN*G4*BSZ];          // [dir][s][g][b]  256MB
__device__ float d_hall[(size_t)SLEN*2*HID*BSZ];       // [t][f=dir*512+j][b] 64MB
__device__ float2 d_xsp[(size_t)128*32*4096];          // X split (hi,lo), fragment order
__device__ float2 d_wsp[(size_t)32*32*4096];           // W split (hi,lo), fragment order
__device__ float d_hsp[2][(size_t)2*64*8*32*4];        // h split, B-fragment order, x2 parity
__device__ float d_bias[NCOLS];
__device__ float d_mean[2*HID], d_rstd[2*HID];
__device__ float d_A[NT*2*HID];
__device__ float d_Cc[NT];
__device__ float d_E[(size_t)BSZ*SLEN*NT];             // [b][s][t]
__device__ int   d_bp[(size_t)BSZ*SLEN*NT];
__device__ int   d_maskI[SLEN*BSZ];                    // [s][b]
__device__ float d_lossParts[BSZ];
__device__ int   d_barCount;

__device__ __forceinline__ float sigm(float x){ return 1.f/(1.f+expf(-x)); }

__device__ __forceinline__ unsigned tf32r(float x){
    unsigned u;
    asm("cvt.rna.tf32.f32 %0, %1;" : "=r"(u) : "f"(x));
    return u;
}

__device__ __forceinline__ void mma_tf32(float* d,
        unsigned a0, unsigned a1, unsigned a2, unsigned a3,
        unsigned b0, unsigned b1){
    asm("mma.sync.aligned.m16n8k8.row.col.f32.tf32.tf32.f32 "
        "{%0,%1,%2,%3},{%4,%5,%6,%7},{%8,%9},{%0,%1,%2,%3};"
        : "+f"(d[0]), "+f"(d[1]), "+f"(d[2]), "+f"(d[3])
        : "r"(a0), "r"(a1), "r"(a2), "r"(a3), "r"(b0), "r"(b1));
}

__device__ __forceinline__ void cpa16(unsigned saddr, const void* g){
    asm volatile("cp.async.cg.shared.global [%0], [%1], 16;" :: "r"(saddr), "l"(g));
}

// ---------------- prep: bias fold, mask normalize, barrier reset ----------------
__global__ void prep_kernel(const float* __restrict__ bif, const float* __restrict__ bhf,
                            const float* __restrict__ bib, const float* __restrict__ bhb,
                            const void* __restrict__ maskraw)
{
    int idx = blockIdx.x*blockDim.x + threadIdx.x;     // grid covers 65536
    if (idx == 0) d_barCount = 0;
    if (idx < NCOLS){
        int dir = idx >> 11, g = idx & 2047;
        d_bias[idx] = dir ? (bib[g]+bhb[g]) : (bif[g]+bhf[g]);
    }
    if (idx < SLEN*BSZ){
        const unsigned char* rb = (const unsigned char*)maskraw;
        bool isbool = (rb[1] != 0);
        int v;
        if (isbool) v = (rb[idx] != 0);
        else        v = (((const int*)maskraw)[idx] != 0);
        d_maskI[idx] = v;
    }
}

// ---------------- fused pre-split of X and W into (hi,lo) tf32 fragment order ----------------
__global__ void split_xw_kernel(const float* __restrict__ X,
                                const float* __restrict__ Wf, const float* __restrict__ Wb)
{
    int kb = blockIdx.x;
    int tid = threadIdx.x;
    if (blockIdx.y < 128){
        int mb = blockIdx.y;
        float2* dst = d_xsp + ((size_t)(mb*32 + kb))*4096;
#pragma unroll
        for (int r=0;r<4;r++){
            int idx = tid + r*256;
            int row = idx>>3, q = idx&7;
            float4 v = *(const float4*)&X[(size_t)(mb*128+row)*DIM + kb*32 + q*4];
            float va[4] = {v.x, v.y, v.z, v.w};
            int regA = (row>>4)*4 + (q>>1);
            int base = regA*128 + (q&1)*64 + ((row&8)>>3);
#pragma unroll
            for (int j=0;j<4;j++){
                unsigned hu = tf32r(va[j]);
                unsigned lu = tf32r(va[j] - __uint_as_float(hu));
                int lane = (row&7)*4 + j;
                dst[base + lane*2] =
                    make_float2(__uint_as_float(hu), __uint_as_float(lu));
            }
        }
    } else {
        int nb = blockIdx.y - 128;
        int n0 = nb*128;
        const float* W = (n0 & 2048) ? Wb : Wf;
        int gb = n0 & 2047;
        float2* dst = d_wsp + ((size_t)(nb*32 + kb))*4096;
#pragma unroll
        for (int r=0;r<4;r++){
            int idx = tid + r*256;
            int row = idx>>3, q = idx&7;
            float4 v = *(const float4*)&W[(size_t)(gb+row)*DIM + kb*32 + q*4];
            float vb[4] = {v.x, v.y, v.z, v.w};
            int regB = (row>>3)*4 + (q>>1);
            int vB = (q&1);
#pragma unroll
            for (int j=0;j<4;j++){
                unsigned hu = tf32r(vb[j]);
                unsigned lu = tf32r(vb[j] - __uint_as_float(hu));
                dst[regB*64 + ((row&7)*4+j)*2 + vB] =
                    make_float2(__uint_as_float(hu), __uint_as_float(lu));
            }
        }
    }
}

// ---------------- tensor-core input GEMM (tf32 3-split, pre-split operands) ----------------
// k-chunk 16, 2-stage cp.async (32KB/stage, 64KB total) -> 2 blocks/SM.
#define GEMM_SMEM_BYTES 65536

__global__ void __launch_bounds__(256,2) gemm_xg_tc()
{
    extern __shared__ float2 sm2[];
    const unsigned smb = (unsigned)__cvta_generic_to_shared(sm2);
    const int tid = threadIdx.x;
    const int lane = tid & 31, warp = tid >> 5;
    const int warp_m = warp >> 2, warp_n = warp & 3;
    const int m0 = blockIdx.y * 128;
    const int n0 = blockIdx.x * 128;
    const float2* xsrc0 = d_xsp + (size_t)blockIdx.y*32*4096;
    const float2* wsrc0 = d_wsp + (size_t)blockIdx.x*32*4096;

    float d[4][4][4];
#pragma unroll
    for (int i=0;i<4;i++)
#pragma unroll
        for (int j=0;j<4;j++)
#pragma unroll
            for (int k=0;k<4;k++) d[i][j][k]=0.f;

    const int aRead = warp_m*8*128 + lane*2;
    const int bRead = warp_n*8*64  + lane*2;

    unsigned smoff[4]; int offx[4], offw[4];
#pragma unroll
    for (int r=0;r<4;r++){
        int idx = tid + r*256;
        smoff[r] = (unsigned)idx*16u;
        int c = idx*2;
        offx[r] = ((c>>8)*4)*128 + (c&255);
        offw[r] = ((c>>7)*4)*64  + (c&127);
    }

    auto issue = [&](int it, int buf){
        const float2* xs = xsrc0 + (size_t)(it>>1)*4096;
        const float2* ws = wsrc0 + (size_t)(it>>1)*4096;
        int h = it & 1;
        unsigned dA = smb + buf*32768u;
        unsigned dB = dA + 16384u;
#pragma unroll
        for (int r=0;r<4;r++){
            cpa16(dA + smoff[r], xs + offx[r] + h*256);
            cpa16(dB + smoff[r], ws + offw[r] + h*128);
        }
        asm volatile("cp.async.commit_group;");
    };

    issue(0, 0);

#pragma unroll 1
    for (int it=0; it<64; it++){
        asm volatile("cp.async.wait_group 0;");
        __syncthreads();
        if (it < 63) issue(it+1, (it+1)&1);

        const float2* As = sm2 + (it&1)*4096;
        const float2* Bs = As + 2048;
#pragma unroll
        for (int g8=0; g8<2; g8++){
            float4 bf[4];
#pragma unroll
            for (int ni=0; ni<4; ni++)
                bf[ni] = *(const float4*)&Bs[bRead + (ni*2+g8)*64];
#pragma unroll
            for (int mi=0; mi<4; mi++){
                const float2* ap = &As[aRead + (mi*2+g8)*128];
                float4 a01 = *(const float4*)ap;
                float4 a23 = *(const float4*)(ap+64);
#pragma unroll
                for (int ni=0; ni<4; ni++){
                    float* dd = d[mi][ni];
                    mma_tf32(dd, __float_as_uint(a01.x), __float_as_uint(a01.z),
                                 __float_as_uint(a23.x), __float_as_uint(a23.z),
                                 __float_as_uint(bf[ni].x), __float_as_uint(bf[ni].z));
                    mma_tf32(dd, __float_as_uint(a01.x), __float_as_uint(a01.z),
                                 __float_as_uint(a23.x), __float_as_uint(a23.z),
                                 __float_as_uint(bf[ni].y), __float_as_uint(bf[ni].w));
                    mma_tf32(dd, __float_as_uint(a01.y), __float_as_uint(a01.w),
                                 __float_as_uint(a23.y), __float_as_uint(a23.w),
                                 __float_as_uint(bf[ni].x), __float_as_uint(bf[ni].z));
                }
            }
        }
    }

    // ---- epilogue: two n-phases of 64 columns through smem ----
    float* Ct = (float*)sm2;          // [64 n][132]
#pragma unroll 1
    for (int p=0; p<2; p++){
        __syncthreads();
        if ((warp_n>>1) == p){
            int nloc0 = (warp_n&1)*32;
#pragma unroll
            for (int mi=0; mi<4; mi++){
#pragma unroll
                for (int ni=0; ni<4; ni++){
                    int mbase = warp_m*64 + mi*16 + (lane>>2);
                    int nb = nloc0 + ni*8 + (lane&3)*2;
                    Ct[(nb  )*132 + mbase    ] = d[mi][ni][0];
                    Ct[(nb+1)*132 + mbase    ] = d[mi][ni][1];
                    Ct[(nb  )*132 + mbase + 8] = d[mi][ni][2];
                    Ct[(nb+1)*132 + mbase + 8] = d[mi][ni][3];
                }
            }
        }
        __syncthreads();
#pragma unroll
        for (int rr=0; rr<8; rr++){
            int lin = tid + rr*256;
            int n = lin >> 5, mq = lin & 31;
            float4 v = *(float4*)&Ct[n*132 + mq*4];
            int ng = n0 + p*64 + n;
            float bias = d_bias[ng];
            v.x += bias; v.y += bias; v.z += bias; v.w += bias;
            int dir = ng >> 11, g = ng & 2047;
            int mg = m0 + mq*4;
            int s = mg >> 6, b = mg & 63;
            *(float4*)&d_xg[(((size_t)dir*SLEN + s)*G4 + g)*BSZ + b] = v;
        }
    }
}

// ---------------- persistent bidirectional LSTM — tensor-core recurrence ----------------
// 128 blocks x 256 threads. W_hh pre-split into SMEM A-fragments once; h
// produced pre-split (hi,lo) into d_hsp (parity double buffer) in B-fragment
// order, consumed via 2-stage cp.async. Warp tile: (km2 x wm2 x wn2), each
// warp 16 rows x 32 batches over half of each stage's kc -> 25% fewer LDS
// wavefronts. km partials reduced through smem scratch. BN fused.
#define WF_FLOATS   32768                      // 8192 float4: [kc64][mt2][p2][lane32]
#define HB_FLOATS   16384                      // 4096 float4: 2 bufs x [kcl8][nt8][lane32]
#define GS2_OFF     (WF_FLOATS + HB_FLOATS)    // 49152
#define LSTM_SMEM_FLOATS (GS2_OFF + 32*66)     // 51264 -> 205056 B

__global__ void __launch_bounds__(256,1) lstm_persist(const float* __restrict__ Whf,
                                                      const float* __restrict__ Whb)
{
    extern __shared__ float sm[];
    float4* Wf4 = (float4*)sm;
    float4* Hb  = (float4*)(sm + WF_FLOATS);
    float*  Gs  = sm + GS2_OFF;
    const unsigned hb_smb = (unsigned)__cvta_generic_to_shared(sm + WF_FLOATS);

    const int tid = threadIdx.x;
    const int dir = blockIdx.x >> 6;
    const int chunk = blockIdx.x & 63;
    const int j0 = chunk * 8;
    const int warp = tid >> 5, lane = tid & 31;
    const int km = warp >> 2;           // k-half within stage
    const int wm = (warp >> 1) & 1;     // row 16-group
    const int wn = warp & 1;            // batch 32-group
    const float* W = dir ? Whb : Whf;

    // one-time W_hh split into A-fragment order
    for (int idx = tid; idx < 32*512; idx += 256){
        int r = idx >> 9;            // 0..31 = gate*8+jj
        int k = idx & 511;
        int gate = r >> 3, jj = r & 7;
        float w = W[(size_t)(gate*HID + j0 + jj)*HID + k];
        unsigned hu = tf32r(w);
        float hif = __uint_as_float(hu);
        float lof = __uint_as_float(tf32r(w - hif));
        int kc = k >> 3, kq = k & 7;
        int rr = r & 15, mt = r >> 4;
        int p  = (kq >= 4);
        int ps = (rr >= 8);
        int lt = (rr & 7)*4 + (kq & 3);
        float* dst = (float*)&Wf4[((kc*2 + mt)*2 + p)*32 + lt];
        dst[ps*2+0] = hif;
        dst[ps*2+1] = lof;
    }
    __syncthreads();

    float creg[2] = {0.f, 0.f};
    float sh[2]  = {0.f, 0.f};     // fused BN: sum of h
    float sh2[2] = {0.f, 0.f};     // fused BN: sum of h^2

    for (int step = 0; step < SLEN; step++){
        int t = dir ? (SLEN-1-step) : step;

        // prefetch this step's xg contributions into registers
        float xv[2][4];
        {
            size_t xgb = (((size_t)dir*SLEN)+t)*G4*BSZ;
#pragma unroll
            for (int it=0; it<2; it++){
                int cell = tid + it*256;
                int jj = cell >> 6, b = cell & 63;
                int j = j0 + jj;
#pragma unroll
                for (int g=0; g<4; g++)
                    xv[it][g] = __ldg(&d_xg[xgb + (size_t)(g*HID+j)*BSZ + b]);
            }
        }

        if (step > 0){
            const float* hspD = d_hsp[(step&1)^1] + (size_t)dir*64*8*32*4;
            float dacc[4][4];
#pragma unroll
            for (int i=0;i<4;i++)
#pragma unroll
                for (int j=0;j<4;j++) dacc[i][j]=0.f;

            // prologue: stage 0 -> buf0
#pragma unroll
            for (int r=0;r<8;r++){
                int c = tid + r*256;
                cpa16(hb_smb + c*16, hspD + c*4);
            }
            asm volatile("cp.async.commit_group;");

#pragma unroll 1
            for (int ts=0; ts<8; ts++){
                asm volatile("cp.async.wait_group 0;");
                __syncthreads();
                if (ts < 7){
                    const float* s2 = hspD + (size_t)(ts+1)*8192;
                    unsigned base = hb_smb + ((ts+1)&1)*32768;
#pragma unroll
                    for (int r=0;r<8;r++){
                        int c = tid + r*256;
                        cpa16(base + c*16, s2 + c*4);
                    }
                    asm volatile("cp.async.commit_group;");
                }

                const float4* hbuf = Hb + (ts&1)*2048;
#pragma unroll
                for (int kcl=0; kcl<4; kcl++){
                    int kis = km*4 + kcl;        // kc within stage
                    int kc = ts*8 + kis;
                    float4 Ap0 = Wf4[((kc*2 + wm)*2 + 0)*32 + lane];
                    float4 Ap1 = Wf4[((kc*2 + wm)*2 + 1)*32 + lane];
#pragma unroll
                    for (int ni=0; ni<4; ni++){
                        float4 Bf = hbuf[(kis*8 + wn*4 + ni)*32 + lane];
                        float* dd = dacc[ni];
                        mma_tf32(dd, __float_as_uint(Ap0.x), __float_as_uint(Ap0.z),
                                     __float_as_uint(Ap1.x), __float_as_uint(Ap1.z),
                                     __float_as_uint(Bf.x),  __float_as_uint(Bf.z));
                        mma_tf32(dd, __float_as_uint(Ap0.x), __float_as_uint(Ap0.z),
                                     __float_as_uint(Ap1.x), __float_as_uint(Ap1.z),
                                     __float_as_uint(Bf.y),  __float_as_uint(Bf.w));
                        mma_tf32(dd, __float_as_uint(Ap0.y), __float_as_uint(Ap0.w),
                                     __float_as_uint(Ap1.y), __float_as_uint(Ap1.w),
                                     __float_as_uint(Bf.x),  __float_as_uint(Bf.z));
                    }
                }
            }

            // ---- reduce km partials through smem scratch (aliases dead Hb) ----
            __syncthreads();                       // all MMA reads of Hb done
            float4* red4 = Hb;                     // 512 float4 scratch
            int sbase = ((wm*2 + wn)*32 + lane)*4;
            if (km == 1){
#pragma unroll
                for (int ni=0; ni<4; ni++)
                    red4[sbase + ni] = *(float4*)dacc[ni];
            }
            __syncthreads();
            if (km == 0){
                int rb = wm*16 + (lane>>2);
#pragma unroll
                for (int ni=0; ni<4; ni++){
                    float4 p = red4[sbase + ni];
                    dacc[ni][0]+=p.x; dacc[ni][1]+=p.y;
                    dacc[ni][2]+=p.z; dacc[ni][3]+=p.w;
                    int bb = wn*32 + ni*8 + 2*(lane&3);
                    *(float2*)&Gs[(rb  )*66 + bb] = make_float2(dacc[ni][0], dacc[ni][1]);
                    *(float2*)&Gs[(rb+8)*66 + bb] = make_float2(dacc[ni][2], dacc[ni][3]);
                }
            }
            __syncthreads();
        }

        // pointwise: gates -> (c,h); produce h pre-split into d_hsp[step&1]
        float* hspW = d_hsp[step&1] + (size_t)dir*64*8*32*4;
#pragma unroll
        for (int it=0; it<2; it++){
            int cell = tid + it*256;
            int jj = cell >> 6, b = cell & 63;
            int j = j0 + jj;
            float g0, g1, g2, g3;
            if (step > 0){
                g0 = Gs[(     jj)*66 + b];
                g1 = Gs[( 8 + jj)*66 + b];
                g2 = Gs[(16 + jj)*66 + b];
                g3 = Gs[(24 + jj)*66 + b];
            } else { g0=g1=g2=g3=0.f; }
            float gi = g0 + xv[it][0];
            float gf = g1 + xv[it][1];
            float gg = g2 + xv[it][2];
            float go = g3 + xv[it][3];
            float ig = sigm(gi), fg = sigm(gf), og = sigm(go);
            float gt = tanhf(gg);
            float cn = fg*creg[it] + ig*gt;
            float hn = og * tanhf(cn);
            creg[it] = cn;
            d_hall[(((size_t)t*2 + dir)*HID + j)*BSZ + b] = hn;
            sh[it]  += hn;
            sh2[it] += hn*hn;

            unsigned hu = tf32r(hn);
            float hif = __uint_as_float(hu);
            float lof = __uint_as_float(tf32r(hn - hif));
            int kc = j >> 3, kk = j & 7;
            int nt = b >> 3, bn = b & 7;
            int lt = bn*4 + (kk & 3);
            size_t off = (((size_t)kc*8 + nt)*32 + lt)*4 + ((kk>>2)&1)*2;
            *(float2*)&hspW[off] = make_float2(hif, lof);
        }

        // grid barrier: cumulative release + acquire poll
        __syncthreads();
        if (tid == 0){
            asm volatile("red.release.gpu.add.s32 [%0], %1;" :: "l"(&d_barCount), "r"(1) : "memory");
            int target = 128*(step+1);
            int v;
            do {
                asm volatile("ld.acquire.gpu.s32 %0, [%1];" : "=r"(v) : "l"(&d_barCount) : "memory");
            } while (v < target);
        }
        __syncthreads();
    }

    // ---- fused BN statistics: block owns features dir*512 + j0..j0+7 ----
    {
        float* redA = (float*)Hb;          // 512 floats (staging dead now)
        float* redB = redA + 512;          // 512 floats
#pragma unroll
        for (int it=0; it<2; it++){
            int cell = tid + it*256;
            redA[cell] = sh[it];
            redB[cell] = sh2[it];
        }
        __syncthreads();
        float s = redA[warp*64 + lane] + redA[warp*64 + 32 + lane];
        float q = redB[warp*64 + lane] + redB[warp*64 + 32 + lane];
#pragma unroll
        for (int o=16;o>0;o>>=1){
            s += __shfl_down_sync(0xffffffffu, s, o);
            q += __shfl_down_sync(0xffffffffu, q, o);
        }
        if (lane == 0){
            float mean = s / (float)NROWS;
            float var  = q / (float)NROWS - mean*mean;
            int f = dir*HID + j0 + warp;
            d_mean[f] = mean;
            d_rstd[f] = rsqrtf(var + 1e-5f);
        }
    }
}

// ---------------- fold BN into linear: A[t][f], Cc[t] ----------------
__global__ void ac_kernel(const float* __restrict__ gamma, const float* __restrict__ beta,
                          const float* __restrict__ lw, const float* __restrict__ lb)
{
    int t = blockIdx.x, tid = threadIdx.x;
    float cs = 0.f;
    for (int f=tid; f<2*HID; f+=128){
        float sc = gamma[f]*d_rstd[f];
        float sh = beta[f] - d_mean[f]*sc;
        float w = lw[t*2*HID + f];
        d_A[t*2*HID + f] = w*sc;
        cs += sh*w;
    }
    __shared__ float red[128];
    red[tid]=cs; __syncthreads();
    for (int o=64;o>0;o>>=1){ if (tid<o) red[tid]+=red[tid+o]; __syncthreads(); }
    if (tid==0) d_Cc[t] = lb[t] + red[0];
}

// ---------------- emissions E[b][s][t]: 256 threads, 4-way f-split ----------------
__global__ void logits_kernel()
{
    __shared__ float As[NT][256];
    __shared__ float Ps[4][NT][64];
    int s = blockIdx.x;
    int tid = threadIdx.x;
    int b = tid & 63, sub = tid >> 6;
    float acc[NT];
#pragma unroll
    for (int t=0;t<NT;t++) acc[t]=0.f;

    for (int f0=0; f0<2*HID; f0+=256){
        for (int idx=tid; idx<NT*256; idx+=256){
            int t = idx >> 8, fi = idx & 255;
            As[t][fi] = d_A[t*2*HID + f0 + fi];
        }
        __syncthreads();
        const float* hb = &d_hall[((size_t)s*2*HID + f0 + sub*64)*BSZ + b];
#pragma unroll 4
        for (int fi=0; fi<64; fi++){
            float hv = hb[(size_t)fi*BSZ];
#pragma unroll
            for (int t=0;t<NT;t++) acc[t] = fmaf(hv, As[t][sub*64+fi], acc[t]);
        }
        __syncthreads();
    }
#pragma unroll
    for (int t=0;t<NT;t++) Ps[sub][t][b] = acc[t];
    __syncthreads();
    if (sub == 0){
#pragma unroll
        for (int t=0;t<NT;t++){
            float v = acc[t] + Ps[1][t][b] + Ps[2][t][b] + Ps[3][t][b] + d_Cc[t];
            d_E[((size_t)b*SLEN + s)*NT + t] = v;
        }
    }
}

// ---------------- CRF: numerator, forward logZ, viterbi — one warp per batch ----------------
__global__ void crf_kernel(const int* __restrict__ labels, const float* __restrict__ start,
                           const float* __restrict__ endv, const float* __restrict__ trans,
                           float* __restrict__ out)
{
    int b = blockIdx.x;
    int lane = threadIdx.x;
    __shared__ float tr[NT*NT];
    __shared__ float alpha[NT], score[NT];
    for (int i=lane;i<NT*NT;i+=32) tr[i]=trans[i];
    __syncwarp();

    float numpart=0.f; int cnt=0;
    for (int s=lane; s<SLEN; s+=32){
        int m = d_maskI[s*BSZ + b];
        cnt += m;
        int ys = labels[s*BSZ + b];
        float emit = d_E[((size_t)b*SLEN + s)*NT + ys];
        if (s==0) numpart += start[ys] + emit;
        else if (m){
            int yp = labels[(s-1)*BSZ + b];
            numpart += tr[yp*NT + ys] + emit;
        }
    }
    for (int o=16;o>0;o>>=1){
        numpart += __shfl_down_sync(0xffffffffu, numpart, o);
        cnt     += __shfl_down_sync(0xffffffffu, cnt, o);
    }
    float num = 0.f;
    if (lane==0){
        int last = cnt - 1;
        num = numpart + endv[labels[last*BSZ + b]];
    }

    if (lane < NT){
        float a0 = start[lane] + d_E[((size_t)b*SLEN)*NT + lane];
        alpha[lane] = a0;
        score[lane] = a0;
    }
    __syncwarp();

    for (int s=1;s<SLEN;s++){
        float lse=0.f, best=0.f; int bp=0;
        if (lane < NT){
            float e = d_E[((size_t)b*SLEN + s)*NT + lane];
            float mx = -1e30f;
#pragma unroll
            for (int t1=0;t1<NT;t1++) mx = fmaxf(mx, alpha[t1] + tr[t1*NT + lane]);
            float sm = 0.f;
#pragma unroll
            for (int t1=0;t1<NT;t1++) sm += __expf(alpha[t1] + tr[t1*NT + lane] - mx);
            lse = mx + __logf(sm) + e;
            float bv = -1e30f;
#pragma unroll
            for (int t1=0;t1<NT;t1++){
                float v = score[t1] + tr[t1*NT + lane];
                if (v > bv){ bv = v; bp = t1; }
            }
            best = bv + e;
            d_bp[((size_t)b*SLEN + s)*NT + lane] = bp;
        }
        __syncwarp();
        if (lane < NT){
            int m = d_maskI[s*BSZ + b];
            if (m){ alpha[lane] = lse; score[lane] = best; }
        }
        __syncwarp();
    }

    float av = (lane<NT) ? alpha[lane] + endv[lane] : -1e30f;
    float mx = av;
    for (int o=16;o>0;o>>=1) mx = fmaxf(mx, __shfl_xor_sync(0xffffffffu, mx, o));
    float ex = (lane<NT) ? __expf(av - mx) : 0.f;
    for (int o=16;o>0;o>>=1) ex += __shfl_xor_sync(0xffffffffu, ex, o);
    float Z = mx + __logf(ex);
    if (lane==0) d_lossParts[b] = Z - num;

    if (lane==0){
        float bv=-1e30f; int tag=0;
        for (int t=0;t<NT;t++){
            float v = score[t] + endv[t];
            if (v > bv){ bv=v; tag=t; }
        }
        for (int s=SLEN-1; s>=1; --s){
            int m = d_maskI[s*BSZ + b];
            out[1 + b*SLEN + s] = m ? (float)tag : 0.f;
            tag = m ? d_bp[((size_t)b*SLEN + s)*NT + tag] : tag;
        }
        int m0 = d_maskI[b];
        out[1 + b*SLEN] = m0 ? (float)tag : 0.f;
    }
}

__global__ void loss_reduce_kernel(float* __restrict__ out)
{
    int l = threadIdx.x;
    float v = d_lossParts[l] + d_lossParts[l+32];
    for (int o=16;o>0;o>>=1) v += __shfl_xor_sync(0xffffffffu, v, o);
    if (l==0) out[0] = v;
}

// ---------------- launch ----------------
extern "C" void kernel_launch(void* const* d_in, const int* in_sizes, int n_in,
                              void* d_out, int out_size)
{
    const float* word   = (const float*)d_in[0];
    const void*  mask   = d_in[1];
    const int*   labels = (const int*)d_in[2];
    const float* w_ih_f = (const float*)d_in[3];
    const float* w_hh_f = (const float*)d_in[4];
    const float* b_ih_f = (const float*)d_in[5];
    const float* b_hh_f = (const float*)d_in[6];
    const float* w_ih_b = (const float*)d_in[7];
    const float* w_hh_b = (const float*)d_in[8];
    const float* b_ih_b = (const float*)d_in[9];
    const float* b_hh_b = (const float*)d_in[10];
    const float* gamma  = (const float*)d_in[11];
    const float* beta   = (const float*)d_in[12];
    const float* lin_w  = (const float*)d_in[13];
    const float* lin_b  = (const float*)d_in[14];
    const float* cstart = (const float*)d_in[15];
    const float* cend   = (const float*)d_in[16];
    const float* ctrans = (const float*)d_in[17];
    float* out = (float*)d_out;

    prep_kernel<<<256,256>>>(b_ih_f,b_hh_f,b_ih_b,b_hh_b, mask);

    dim3 gs(32, 160);
    split_xw_kernel<<<gs,256>>>(word, w_ih_f, w_ih_b);

    cudaFuncSetAttribute(gemm_xg_tc, cudaFuncAttributeMaxDynamicSharedMemorySize,
                         GEMM_SMEM_BYTES);
    dim3 g1(NCOLS/128, NROWS/128);     // (32, 128)
    gemm_xg_tc<<<g1,256,GEMM_SMEM_BYTES>>>();

    cudaFuncSetAttribute(lstm_persist, cudaFuncAttributeMaxDynamicSharedMemorySize,
                         LSTM_SMEM_FLOATS*4);
    lstm_persist<<<128,256,LSTM_SMEM_FLOATS*4>>>(w_hh_f, w_hh_b);

    ac_kernel<<<NT,128>>>(gamma,beta,lin_w,lin_b);
    logits_kernel<<<SLEN,256>>>();
    crf_kernel<<<BSZ,32>>>(labels, cstart, cend, ctrans, out);
    loss_reduce_kernel<<<1,32>>>(out);
}

// round 16
// speedup vs baseline: 1.0171x; 1.0171x over previous
#include <cuda_runtime.h>
#include <math.h>

#define SLEN 256
#define BSZ  64
#define DIM  1024
#define HID  512
#define NT   17
#define G4   (4*HID)    // 2048 gate rows per direction
#define NCOLS (2*G4)    // 4096 combined columns (fwd+bwd)
#define NROWS (SLEN*BSZ)

// ---------------- device scratch (no allocations allowed) ----------------
__device__ float d_xg[(size_t)2*SLEN*G4*BSZ];          // [dir][s][g][b]  256MB
__device__ float d_hall[(size_t)SLEN*2*HID*BSZ];       // [t][f=dir*512+j][b] 64MB
__device__ float2 d_xsp[(size_t)128*32*4096];          // X split (hi,lo), fragment order
__device__ float2 d_wsp[(size_t)32*32*4096];           // W split (hi,lo), fragment order
__device__ float d_hsp[2][(size_t)2*64*8*32*4];        // h split, B-fragment order, x2 parity
__device__ float d_bias[NCOLS];
__device__ float d_mean[2*HID], d_rstd[2*HID];
__device__ float d_A[NT*2*HID];
__device__ float d_Cc[NT];
__device__ float d_E[(size_t)BSZ*SLEN*NT];             // [b][s][t]
__device__ int   d_bp[(size_t)BSZ*SLEN*NT];
__device__ int   d_maskI[SLEN*BSZ];                    // [s][b]
__device__ float d_lossParts[BSZ];
__device__ int   d_barCnt2[2];                         // per-direction barrier

__device__ __forceinline__ float sigm(float x){ return 1.f/(1.f+expf(-x)); }

__device__ __forceinline__ unsigned tf32r(float x){
    unsigned u;
    asm("cvt.rna.tf32.f32 %0, %1;" : "=r"(u) : "f"(x));
    return u;
}

__device__ __forceinline__ void mma_tf32(float* d,
        unsigned a0, unsigned a1, unsigned a2, unsigned a3,
        unsigned b0, unsigned b1){
    asm("mma.sync.aligned.m16n8k8.row.col.f32.tf32.tf32.f32 "
        "{%0,%1,%2,%3},{%4,%5,%6,%7},{%8,%9},{%0,%1,%2,%3};"
        : "+f"(d[0]), "+f"(d[1]), "+f"(d[2]), "+f"(d[3])
        : "r"(a0), "r"(a1), "r"(a2), "r"(a3), "r"(b0), "r"(b1));
}

__device__ __forceinline__ void cpa16(unsigned saddr, const void* g){
    asm volatile("cp.async.cg.shared.global [%0], [%1], 16;" :: "r"(saddr), "l"(g));
}

// ---------------- prep: bias fold, mask normalize, barrier reset ----------------
__global__ void prep_kernel(const float* __restrict__ bif, const float* __restrict__ bhf,
                            const float* __restrict__ bib, const float* __restrict__ bhb,
                            const void* __restrict__ maskraw)
{
    int idx = blockIdx.x*blockDim.x + threadIdx.x;     // grid covers 65536
    if (idx < 2) d_barCnt2[idx] = 0;
    if (idx < NCOLS){
        int dir = idx >> 11, g = idx & 2047;
        d_bias[idx] = dir ? (bib[g]+bhb[g]) : (bif[g]+bhf[g]);
    }
    if (idx < SLEN*BSZ){
        const unsigned char* rb = (const unsigned char*)maskraw;
        bool isbool = (rb[1] != 0);
        int v;
        if (isbool) v = (rb[idx] != 0);
        else        v = (((const int*)maskraw)[idx] != 0);
        d_maskI[idx] = v;
    }
}

// ---------------- fused pre-split of X and W into (hi,lo) tf32 fragment order ----------------
// blockIdx.y < 128: X tile (mb=blockIdx.y); else W tile (nb=blockIdx.y-128).
__global__ void split_xw_kernel(const float* __restrict__ X,
                                const float* __restrict__ Wf, const float* __restrict__ Wb)
{
    int kb = blockIdx.x;
    int tid = threadIdx.x;
    if (blockIdx.y < 128){
        int mb = blockIdx.y;
        float2* dst = d_xsp + ((size_t)(mb*32 + kb))*4096;
#pragma unroll
        for (int r=0;r<4;r++){
            int idx = tid + r*256;
            int row = idx>>3, q = idx&7;
            float4 v = *(const float4*)&X[(size_t)(mb*128+row)*DIM + kb*32 + q*4];
            float va[4] = {v.x, v.y, v.z, v.w};
            int regA = (row>>4)*4 + (q>>1);
            int base = regA*128 + (q&1)*64 + ((row&8)>>3);
#pragma unroll
            for (int j=0;j<4;j++){
                unsigned hu = tf32r(va[j]);
                unsigned lu = tf32r(va[j] - __uint_as_float(hu));
                int lane = (row&7)*4 + j;
                dst[base + lane*2] =
                    make_float2(__uint_as_float(hu), __uint_as_float(lu));
            }
        }
    } else {
        int nb = blockIdx.y - 128;
        int n0 = nb*128;
        const float* W = (n0 & 2048) ? Wb : Wf;
        int gb = n0 & 2047;
        float2* dst = d_wsp + ((size_t)(nb*32 + kb))*4096;
#pragma unroll
        for (int r=0;r<4;r++){
            int idx = tid + r*256;
            int row = idx>>3, q = idx&7;
            float4 v = *(const float4*)&W[(size_t)(gb+row)*DIM + kb*32 + q*4];
            float vb[4] = {v.x, v.y, v.z, v.w};
            int regB = (row>>3)*4 + (q>>1);
            int vB = (q&1);
#pragma unroll
            for (int j=0;j<4;j++){
                unsigned hu = tf32r(vb[j]);
                unsigned lu = tf32r(vb[j] - __uint_as_float(hu));
                dst[regB*64 + ((row&7)*4+j)*2 + vB] =
                    make_float2(__uint_as_float(hu), __uint_as_float(lu));
            }
        }
    }
}

// ---------------- tensor-core input GEMM (tf32 3-split, pre-split operands) ----------------
// k-chunk 16, 2-stage cp.async (32KB/stage, 64KB total) -> 2 blocks/SM.
// One __syncthreads per iter; A-fragment reads lane-coalesced.
#define GEMM_SMEM_BYTES 65536

__global__ void __launch_bounds__(256,2) gemm_xg_tc()
{
    extern __shared__ float2 sm2[];
    const unsigned smb = (unsigned)__cvta_generic_to_shared(sm2);
    const int tid = threadIdx.x;
    const int lane = tid & 31, warp = tid >> 5;
    const int warp_m = warp >> 2, warp_n = warp & 3;
    const int m0 = blockIdx.y * 128;
    const int n0 = blockIdx.x * 128;
    const float2* xsrc0 = d_xsp + (size_t)blockIdx.y*32*4096;
    const float2* wsrc0 = d_wsp + (size_t)blockIdx.x*32*4096;

    float d[4][4][4];
#pragma unroll
    for (int i=0;i<4;i++)
#pragma unroll
        for (int j=0;j<4;j++)
#pragma unroll
            for (int k=0;k<4;k++) d[i][j][k]=0.f;

    const int aRead = warp_m*8*128 + lane*2;   // float2 units; + (mi*2+g8)*128 (+64 for k4half1)
    const int bRead = warp_n*8*64  + lane*2;   // float2 units; + (ni*2+g8)*64

    unsigned smoff[4]; int offx[4], offw[4];
#pragma unroll
    for (int r=0;r<4;r++){
        int idx = tid + r*256;     // 0..1023
        smoff[r] = (unsigned)idx*16u;
        int c = idx*2;
        offx[r] = ((c>>8)*4)*128 + (c&255);
        offw[r] = ((c>>7)*4)*64  + (c&127);
    }

    auto issue = [&](int it, int buf){
        const float2* xs = xsrc0 + (size_t)(it>>1)*4096;
        const float2* ws = wsrc0 + (size_t)(it>>1)*4096;
        int h = it & 1;
        unsigned dA = smb + buf*32768u;
        unsigned dB = dA + 16384u;
#pragma unroll
        for (int r=0;r<4;r++){
            cpa16(dA + smoff[r], xs + offx[r] + h*256);
            cpa16(dB + smoff[r], ws + offw[r] + h*128);
        }
        asm volatile("cp.async.commit_group;");
    };

    issue(0, 0);

#pragma unroll 1
    for (int it=0; it<64; it++){
        asm volatile("cp.async.wait_group 0;");
        __syncthreads();
        if (it < 63) issue(it+1, (it+1)&1);

        const float2* As = sm2 + (it&1)*4096;
        const float2* Bs = As + 2048;
#pragma unroll
        for (int g8=0; g8<2; g8++){
            float4 bf[4];
#pragma unroll
            for (int ni=0; ni<4; ni++)
                bf[ni] = *(const float4*)&Bs[bRead + (ni*2+g8)*64];
#pragma unroll
            for (int mi=0; mi<4; mi++){
                const float2* ap = &As[aRead + (mi*2+g8)*128];
                float4 a01 = *(const float4*)ap;        // k4half 0
                float4 a23 = *(const float4*)(ap+64);   // k4half 1
#pragma unroll
                for (int ni=0; ni<4; ni++){
                    float* dd = d[mi][ni];
                    mma_tf32(dd, __float_as_uint(a01.x), __float_as_uint(a01.z),
                                 __float_as_uint(a23.x), __float_as_uint(a23.z),
                                 __float_as_uint(bf[ni].x), __float_as_uint(bf[ni].z));
                    mma_tf32(dd, __float_as_uint(a01.x), __float_as_uint(a01.z),
                                 __float_as_uint(a23.x), __float_as_uint(a23.z),
                                 __float_as_uint(bf[ni].y), __float_as_uint(bf[ni].w));
                    mma_tf32(dd, __float_as_uint(a01.y), __float_as_uint(a01.w),
                                 __float_as_uint(a23.y), __float_as_uint(a23.w),
                                 __float_as_uint(bf[ni].x), __float_as_uint(bf[ni].z));
                }
            }
        }
    }

    // ---- epilogue: two n-phases of 64 columns through smem ----
    float* Ct = (float*)sm2;          // [64 n][132]
#pragma unroll 1
    for (int p=0; p<2; p++){
        __syncthreads();
        if ((warp_n>>1) == p){
            int nloc0 = (warp_n&1)*32;
#pragma unroll
            for (int mi=0; mi<4; mi++){
#pragma unroll
                for (int ni=0; ni<4; ni++){
                    int mbase = warp_m*64 + mi*16 + (lane>>2);
                    int nb = nloc0 + ni*8 + (lane&3)*2;
                    Ct[(nb  )*132 + mbase    ] = d[mi][ni][0];
                    Ct[(nb+1)*132 + mbase    ] = d[mi][ni][1];
                    Ct[(nb  )*132 + mbase + 8] = d[mi][ni][2];
                    Ct[(nb+1)*132 + mbase + 8] = d[mi][ni][3];
                }
            }
        }
        __syncthreads();
#pragma unroll
        for (int rr=0; rr<8; rr++){
            int lin = tid + rr*256;            // 0..2047
            int n = lin >> 5, mq = lin & 31;
            float4 v = *(float4*)&Ct[n*132 + mq*4];
            int ng = n0 + p*64 + n;
            float bias = d_bias[ng];
            v.x += bias; v.y += bias; v.z += bias; v.w += bias;
            int dir = ng >> 11, g = ng & 2047;
            int mg = m0 + mq*4;
            int s = mg >> 6, b = mg & 63;
            *(float4*)&d_xg[(((size_t)dir*SLEN + s)*G4 + g)*BSZ + b] = v;
        }
    }
}

// ---------------- persistent bidirectional LSTM — tensor-core recurrence ----------------
// 128 blocks x 256 threads (R14 champion structure). W_hh pre-split into SMEM
// A-fragments once; h produced pre-split (hi,lo) into d_hsp (parity double
// buffer) in B-fragment order, consumed via 2-stage cp.async. BN fused.
// PER-DIRECTION grid barrier (64 arrivals each, separate L2 lines).
#define WF_FLOATS   32768                      // 8192 float4: [kc64][mt2][p2][lane32]
#define HB_FLOATS   16384                      // 4096 float4: 2 bufs x [kcl8][nt8][lane32]
#define GS2_OFF     (WF_FLOATS + HB_FLOATS)    // 49152
#define LSTM_SMEM_FLOATS (GS2_OFF + 32*66)     // 51264 -> 205056 B

__global__ void __launch_bounds__(256,1) lstm_persist(const float* __restrict__ Whf,
                                                      const float* __restrict__ Whb)
{
    extern __shared__ float sm[];
    float4* Wf4 = (float4*)sm;
    float4* Hb  = (float4*)(sm + WF_FLOATS);
    float*  Gs  = sm + GS2_OFF;
    const unsigned hb_smb = (unsigned)__cvta_generic_to_shared(sm + WF_FLOATS);

    const int tid = threadIdx.x;
    const int dir = blockIdx.x >> 6;
    const int chunk = blockIdx.x & 63;
    const int j0 = chunk * 8;
    const int warp = tid >> 5, lane = tid & 31;
    const int warp_m = warp >> 2, warp_n = warp & 3;
    const float* W = dir ? Whb : Whf;

    // one-time W_hh split into A-fragment order
    for (int idx = tid; idx < 32*512; idx += 256){
        int r = idx >> 9;            // 0..31 = gate*8+jj
        int k = idx & 511;
        int gate = r >> 3, jj = r & 7;
        float w = W[(size_t)(gate*HID + j0 + jj)*HID + k];
        unsigned hu = tf32r(w);
        float hif = __uint_as_float(hu);
        float lof = __uint_as_float(tf32r(w - hif));
        int kc = k >> 3, kq = k & 7;
        int rr = r & 15, mt = r >> 4;
        int p  = (kq >= 4);
        int ps = (rr >= 8);
        int lt = (rr & 7)*4 + (kq & 3);
        float* dst = (float*)&Wf4[((kc*2 + mt)*2 + p)*32 + lt];
        dst[ps*2+0] = hif;
        dst[ps*2+1] = lof;
    }
    __syncthreads();

    float creg[2] = {0.f, 0.f};
    float sh[2]  = {0.f, 0.f};     // fused BN: sum of h
    float sh2[2] = {0.f, 0.f};     // fused BN: sum of h^2

    for (int step = 0; step < SLEN; step++){
        int t = dir ? (SLEN-1-step) : step;

        // prefetch this step's xg contributions into registers
        float xv[2][4];
        {
            size_t xgb = (((size_t)dir*SLEN)+t)*G4*BSZ;
#pragma unroll
            for (int it=0; it<2; it++){
                int cell = tid + it*256;
                int jj = cell >> 6, b = cell & 63;
                int j = j0 + jj;
#pragma unroll
                for (int g=0; g<4; g++)
                    xv[it][g] = __ldg(&d_xg[xgb + (size_t)(g*HID+j)*BSZ + b]);
            }
        }

        if (step > 0){
            const float* hspD = d_hsp[(step&1)^1] + (size_t)dir*64*8*32*4;
            float dacc[2][4] = {{0.f,0.f,0.f,0.f},{0.f,0.f,0.f,0.f}};

            // prologue: stage 0 -> buf0
#pragma unroll
            for (int r=0;r<8;r++){
                int c = tid + r*256;
                cpa16(hb_smb + c*16, hspD + c*4);
            }
            asm volatile("cp.async.commit_group;");

#pragma unroll 1
            for (int ts=0; ts<8; ts++){
                asm volatile("cp.async.wait_group 0;");
                __syncthreads();
                if (ts < 7){
                    const float* s2 = hspD + (size_t)(ts+1)*8192;
                    unsigned base = hb_smb + ((ts+1)&1)*32768;
#pragma unroll
                    for (int r=0;r<8;r++){
                        int c = tid + r*256;
                        cpa16(base + c*16, s2 + c*4);
                    }
                    asm volatile("cp.async.commit_group;");
                }

                const float4* hbuf = Hb + (ts&1)*2048;
#pragma unroll
                for (int kcl=0; kcl<8; kcl++){
                    int kc = ts*8 + kcl;
                    float4 Ap0 = Wf4[((kc*2 + warp_m)*2 + 0)*32 + lane];
                    float4 Ap1 = Wf4[((kc*2 + warp_m)*2 + 1)*32 + lane];
#pragma unroll
                    for (int ni=0; ni<2; ni++){
                        float4 Bf = hbuf[(kcl*8 + warp_n*2 + ni)*32 + lane];
                        float* dd = dacc[ni];
                        mma_tf32(dd, __float_as_uint(Ap0.x), __float_as_uint(Ap0.z),
                                     __float_as_uint(Ap1.x), __float_as_uint(Ap1.z),
                                     __float_as_uint(Bf.x),  __float_as_uint(Bf.z));
                        mma_tf32(dd, __float_as_uint(Ap0.x), __float_as_uint(Ap0.z),
                                     __float_as_uint(Ap1.x), __float_as_uint(Ap1.z),
                                     __float_as_uint(Bf.y),  __float_as_uint(Bf.w));
                        mma_tf32(dd, __float_as_uint(Ap0.y), __float_as_uint(Ap0.w),
                                     __float_as_uint(Ap1.y), __float_as_uint(Ap1.w),
                                     __float_as_uint(Bf.x),  __float_as_uint(Bf.z));
                    }
                }
            }

            // write gates to Gs [32][66]
            int rb = warp_m*16 + (lane>>2);
#pragma unroll
            for (int ni=0; ni<2; ni++){
                int bb = warp_n*16 + ni*8 + 2*(lane&3);
                *(float2*)&Gs[(rb  )*66 + bb] = make_float2(dacc[ni][0], dacc[ni][1]);
                *(float2*)&Gs[(rb+8)*66 + bb] = make_float2(dacc[ni][2], dacc[ni][3]);
            }
            __syncthreads();
        }

        // pointwise: gates -> (c,h); produce h pre-split into d_hsp[step&1]
        float* hspW = d_hsp[step&1] + (size_t)dir*64*8*32*4;
#pragma unroll
        for (int it=0; it<2; it++){
            int cell = tid + it*256;
            int jj = cell >> 6, b = cell & 63;
            int j = j0 + jj;
            float g0, g1, g2, g3;
            if (step > 0){
                g0 = Gs[(     jj)*66 + b];
                g1 = Gs[( 8 + jj)*66 + b];
                g2 = Gs[(16 + jj)*66 + b];
                g3 = Gs[(24 + jj)*66 + b];
            } else { g0=g1=g2=g3=0.f; }
            float gi = g0 + xv[it][0];
            float gf = g1 + xv[it][1];
            float gg = g2 + xv[it][2];
            float go = g3 + xv[it][3];
            float ig = sigm(gi), fg = sigm(gf), og = sigm(go);
            float gt = tanhf(gg);
            float cn = fg*creg[it] + ig*gt;
            float hn = og * tanhf(cn);
            creg[it] = cn;
            d_hall[(((size_t)t*2 + dir)*HID + j)*BSZ + b] = hn;
            sh[it]  += hn;
            sh2[it] += hn*hn;

            unsigned hu = tf32r(hn);
            float hif = __uint_as_float(hu);
            float lof = __uint_as_float(tf32r(hn - hif));
            int kc = j >> 3, kk = j & 7;
            int nt = b >> 3, bn = b & 7;
            int lt = bn*4 + (kk & 3);
            size_t off = (((size_t)kc*8 + nt)*32 + lt)*4 + ((kk>>2)&1)*2;
            *(float2*)&hspW[off] = make_float2(hif, lof);
        }

        // per-direction grid barrier: cumulative release + acquire poll
        __syncthreads();
        if (tid == 0){
            asm volatile("red.release.gpu.add.s32 [%0], %1;" :: "l"(&d_barCnt2[dir]), "r"(1) : "memory");
            int target = 64*(step+1);
            int v;
            do {
                asm volatile("ld.acquire.gpu.s32 %0, [%1];" : "=r"(v) : "l"(&d_barCnt2[dir]) : "memory");
            } while (v < target);
        }
        __syncthreads();
    }

    // ---- fused BN statistics: block owns features dir*512 + j0..j0+7 ----
    {
        float* redA = (float*)Hb;          // 512 floats (staging dead now)
        float* redB = redA + 512;          // 512 floats
#pragma unroll
        for (int it=0; it<2; it++){
            int cell = tid + it*256;
            redA[cell] = sh[it];
            redB[cell] = sh2[it];
        }
        __syncthreads();
        float s = redA[warp*64 + lane] + redA[warp*64 + 32 + lane];
        float q = redB[warp*64 + lane] + redB[warp*64 + 32 + lane];
#pragma unroll
        for (int o=16;o>0;o>>=1){
            s += __shfl_down_sync(0xffffffffu, s, o);
            q += __shfl_down_sync(0xffffffffu, q, o);
        }
        if (lane == 0){
            float mean = s / (float)NROWS;
            float var  = q / (float)NROWS - mean*mean;
            int f = dir*HID + j0 + warp;
            d_mean[f] = mean;
            d_rstd[f] = rsqrtf(var + 1e-5f);
        }
    }
}

// ---------------- fold BN into linear: A[t][f], Cc[t] ----------------
__global__ void ac_kernel(const float* __restrict__ gamma, const float* __restrict__ beta,
                          const float* __restrict__ lw, const float* __restrict__ lb)
{
    int t = blockIdx.x, tid = threadIdx.x;
    float cs = 0.f;
    for (int f=tid; f<2*HID; f+=128){
        float sc = gamma[f]*d_rstd[f];
        float sh = beta[f] - d_mean[f]*sc;
        float w = lw[t*2*HID + f];
        d_A[t*2*HID + f] = w*sc;
        cs += sh*w;
    }
    __shared__ float red[128];
    red[tid]=cs; __syncthreads();
    for (int o=64;o>0;o>>=1){ if (tid<o) red[tid]+=red[tid+o]; __syncthreads(); }
    if (tid==0) d_Cc[t] = lb[t] + red[0];
}

// ---------------- emissions E[b][s][t]: 256 threads, 4-way f-split ----------------
__global__ void logits_kernel()
{
    __shared__ float As[NT][256];
    __shared__ float Ps[4][NT][64];
    int s = blockIdx.x;
    int tid = threadIdx.x;
    int b = tid & 63, sub = tid >> 6;
    float acc[NT];
#pragma unroll
    for (int t=0;t<NT;t++) acc[t]=0.f;

    for (int f0=0; f0<2*HID; f0+=256){
        for (int idx=tid; idx<NT*256; idx+=256){
            int t = idx >> 8, fi = idx & 255;
            As[t][fi] = d_A[t*2*HID + f0 + fi];
        }
        __syncthreads();
        const float* hb = &d_hall[((size_t)s*2*HID + f0 + sub*64)*BSZ + b];
#pragma unroll 4
        for (int fi=0; fi<64; fi++){
            float hv = hb[(size_t)fi*BSZ];
#pragma unroll
            for (int t=0;t<NT;t++) acc[t] = fmaf(hv, As[t][sub*64+fi], acc[t]);
        }
        __syncthreads();
    }
#pragma unroll
    for (int t=0;t<NT;t++) Ps[sub][t][b] = acc[t];
    __syncthreads();
    if (sub == 0){
#pragma unroll
        for (int t=0;t<NT;t++){
            float v = acc[t] + Ps[1][t][b] + Ps[2][t][b] + Ps[3][t][b] + d_Cc[t];
            d_E[((size_t)b*SLEN + s)*NT + t] = v;
        }
    }
}

// ---------------- CRF: numerator, forward logZ, viterbi — one warp per batch ----------------
__global__ void crf_kernel(const int* __restrict__ labels, const float* __restrict__ start,
                           const float* __restrict__ endv, const float* __restrict__ trans,
                           float* __restrict__ out)
{
    int b = blockIdx.x;
    int lane = threadIdx.x;
    __shared__ float tr[NT*NT];
    __shared__ float alpha[NT], score[NT];
    for (int i=lane;i<NT*NT;i+=32) tr[i]=trans[i];
    __syncwarp();

    float numpart=0.f; int cnt=0;
    for (int s=lane; s<SLEN; s+=32){
        int m = d_maskI[s*BSZ + b];
        cnt += m;
        int ys = labels[s*BSZ + b];
        float emit = d_E[((size_t)b*SLEN + s)*NT + ys];
        if (s==0) numpart += start[ys] + emit;
        else if (m){
            int yp = labels[(s-1)*BSZ + b];
            numpart += tr[yp*NT + ys] + emit;
        }
    }
    for (int o=16;o>0;o>>=1){
        numpart += __shfl_down_sync(0xffffffffu, numpart, o);
        cnt     += __shfl_down_sync(0xffffffffu, cnt, o);
    }
    float num = 0.f;
    if (lane==0){
        int last = cnt - 1;
        num = numpart + endv[labels[last*BSZ + b]];
    }

    if (lane < NT){
        float a0 = start[lane] + d_E[((size_t)b*SLEN)*NT + lane];
        alpha[lane] = a0;
        score[lane] = a0;
    }
    __syncwarp();

    for (int s=1;s<SLEN;s++){
        float lse=0.f, best=0.f; int bp=0;
        if (lane < NT){
            float e = d_E[((size_t)b*SLEN + s)*NT + lane];
            float mx = -1e30f;
#pragma unroll
            for (int t1=0;t1<NT;t1++) mx = fmaxf(mx, alpha[t1] + tr[t1*NT + lane]);
            float sm = 0.f;
#pragma unroll
            for (int t1=0;t1<NT;t1++) sm += __expf(alpha[t1] + tr[t1*NT + lane] - mx);
            lse = mx + __logf(sm) + e;
            float bv = -1e30f;
#pragma unroll
            for (int t1=0;t1<NT;t1++){
                float v = score[t1] + tr[t1*NT + lane];
                if (v > bv){ bv = v; bp = t1; }
            }
            best = bv + e;
            d_bp[((size_t)b*SLEN + s)*NT + lane] = bp;
        }
        __syncwarp();
        if (lane < NT){
            int m = d_maskI[s*BSZ + b];
            if (m){ alpha[lane] = lse; score[lane] = best; }
        }
        __syncwarp();
    }

    float av = (lane<NT) ? alpha[lane] + endv[lane] : -1e30f;
    float mx = av;
    for (int o=16;o>0;o>>=1) mx = fmaxf(mx, __shfl_xor_sync(0xffffffffu, mx, o));
    float ex = (lane<NT) ? __expf(av - mx) : 0.f;
    for (int o=16;o>0;o>>=1) ex += __shfl_xor_sync(0xffffffffu, ex, o);
    float Z = mx + __logf(ex);
    if (lane==0) d_lossParts[b] = Z - num;

    if (lane==0){
        float bv=-1e30f; int tag=0;
        for (int t=0;t<NT;t++){
            float v = score[t] + endv[t];
            if (v > bv){ bv=v; tag=t; }
        }
        for (int s=SLEN-1; s>=1; --s){
            int m = d_maskI[s*BSZ + b];
            out[1 + b*SLEN + s] = m ? (float)tag : 0.f;
            tag = m ? d_bp[((size_t)b*SLEN + s)*NT + tag] : tag;
        }
        int m0 = d_maskI[b];
        out[1 + b*SLEN] = m0 ? (float)tag : 0.f;
    }
}

__global__ void loss_reduce_kernel(float* __restrict__ out)
{
    int l = threadIdx.x;
    float v = d_lossParts[l] + d_lossParts[l+32];
    for (int o=16;o>0;o>>=1) v += __shfl_xor_sync(0xffffffffu, v, o);
    if (l==0) out[0] = v;
}

// ---------------- launch ----------------
extern "C" void kernel_launch(void* const* d_in, const int* in_sizes, int n_in,
                              void* d_out, int out_size)
{
    const float* word   = (const float*)d_in[0];
    const void*  mask   = d_in[1];
    const int*   labels = (const int*)d_in[2];
    const float* w_ih_f = (const float*)d_in[3];
    const float* w_hh_f = (const float*)d_in[4];
    const float* b_ih_f = (const float*)d_in[5];
    const float* b_hh_f = (const float*)d_in[6];
    const float* w_ih_b = (const float*)d_in[7];
    const float* w_hh_b = (const float*)d_in[8];
    const float* b_ih_b = (const float*)d_in[9];
    const float* b_hh_b = (const float*)d_in[10];
    const float* gamma  = (const float*)d_in[11];
    const float* beta   = (const float*)d_in[12];
    const float* lin_w  = (const float*)d_in[13];
    const float* lin_b  = (const float*)d_in[14];
    const float* cstart = (const float*)d_in[15];
    const float* cend   = (const float*)d_in[16];
    const float* ctrans = (const float*)d_in[17];
    float* out = (float*)d_out;

    prep_kernel<<<256,256>>>(b_ih_f,b_hh_f,b_ih_b,b_hh_b, mask);

    dim3 gs(32, 160);
    split_xw_kernel<<<gs,256>>>(word, w_ih_f, w_ih_b);

    cudaFuncSetAttribute(gemm_xg_tc, cudaFuncAttributeMaxDynamicSharedMemorySize,
                         GEMM_SMEM_BYTES);
    dim3 g1(NCOLS/128, NROWS/128);     // (32, 128)
    gemm_xg_tc<<<g1,256,GEMM_SMEM_BYTES>>>();

    cudaFuncSetAttribute(lstm_persist, cudaFuncAttributeMaxDynamicSharedMemorySize,
                         LSTM_SMEM_FLOATS*4);
    lstm_persist<<<128,256,LSTM_SMEM_FLOATS*4>>>(w_hh_f, w_hh_b);

    ac_kernel<<<NT,128>>>(gamma,beta,lin_w,lin_b);
    logits_kernel<<<SLEN,256>>>();
    crf_kernel<<<BSZ,32>>>(labels, cstart, cend, ctrans, out);
    loss_reduce_kernel<<<1,32>>>(out);
}